// round 16
// baseline (speedup 1.0000x reference)
#include <cuda_runtime.h>
#include <cstddef>

#define BATCH_N 16384
#define SEQ_N   512
#define HID_N   5
#define FLAT_N  2560        // SEQ_N*HID_N
#define TPB     320         // 10 warps = 2.5 warps/SMSP
#define EPB     120         // elements per block: 10 warps * 6 groups * 2 elems

// Collapsed linear head: Weff = W2 @ W1 (1 x 2560), beff = W2@b1 + b2
__device__ float g_Weff[FLAT_N];
__device__ float g_beff;

// ---------------------------------------------------------------------------
// Kernel 1: collapse the two linear layers (no nonlinearity between them).
// ---------------------------------------------------------------------------
__global__ void weff_kernel(const float* __restrict__ W1,
                            const float* __restrict__ b1,
                            const float* __restrict__ W2,
                            const float* __restrict__ b2)
{
    int j = blockIdx.x * blockDim.x + threadIdx.x;
    if (j < FLAT_N) {
        float acc = 0.0f;
        #pragma unroll 8
        for (int k = 0; k < 512; ++k)
            acc = fmaf(W2[k], W1[(size_t)k * FLAT_N + j], acc);
        g_Weff[j] = acc;
    }
    if (j == 0) {
        float acc = b2[0];
        for (int k = 0; k < 512; ++k)
            acc = fmaf(W2[k], b1[k], acc);
        g_beff = acc;
    }
}

// ---------------------------------------------------------------------------
// Packed f32x2 + fast-activation primitives
// ---------------------------------------------------------------------------
typedef unsigned long long u64;

__device__ __forceinline__ u64 pack2(float lo, float hi) {
    u64 r; asm("mov.b64 %0, {%1, %2};" : "=l"(r) : "f"(lo), "f"(hi)); return r;
}
__device__ __forceinline__ void unpack2(u64 v, float& lo, float& hi) {
    asm("mov.b64 {%0, %1}, %2;" : "=f"(lo), "=f"(hi) : "l"(v));
}
__device__ __forceinline__ u64 fma2(u64 a, u64 b, u64 c) {
    u64 d; asm("fma.rn.f32x2 %0, %1, %2, %3;" : "=l"(d) : "l"(a), "l"(b), "l"(c)); return d;
}
__device__ __forceinline__ float tanh_fast(float x) {
    float y; asm("tanh.approx.f32 %0, %1;" : "=f"(y) : "f"(x)); return y;
}

// ---------------------------------------------------------------------------
// Kernel 2: 5-lane group owns TWO batch elements (A, B), interleaved in one
// instruction stream for dual-recurrence ILP. Thread role u owns hidden unit
// u of both elements in both layers; all weights are shared between A and B.
//   * fully software-pipelined (ga0 and ga1p precomputed, as in R14)
//   * sigmoid pre-scale folded into i/f/o weight rows
//   * layer-1 weights register-resident; layer-0 via padded LDS.128 (loaded
//     once per step, used for both elements); head weight LDS shared by A/B
// ---------------------------------------------------------------------------
__global__ void __launch_bounds__(TPB, 1)
lstm_fused_kernel(const float* __restrict__ x,
                  const float* __restrict__ Wih0, const float* __restrict__ Whh0,
                  const float* __restrict__ bih0, const float* __restrict__ bhh0,
                  const float* __restrict__ Wih1, const float* __restrict__ Whh1,
                  const float* __restrict__ bih1, const float* __restrict__ bhh1,
                  float* __restrict__ out)
{
    // L0: role stride 18 u64 (=144B, conflict-free); pair p at +8p, slots:
    //   0=B, 1=Wih, 2..6=Whh c0..c4, 7=pad
    __shared__ __align__(16) u64 sL0[5 * 18];
    // L1 staging (copied to regs): [role][pair][0=B,1..5=Wih1,6..10=Whh1]
    __shared__ __align__(16) u64 sL1[5][2][11];
    // Head weights: sWf[u*513 + s] = Weff[5s+u]; stride 513 -> distinct banks
    __shared__ float sWf[5 * (SEQ_N + 1)];

    const int t = threadIdx.x;

    // ---- build tables (10 builder threads: role u, pair p) ----
    if (t < 10) {
        const int u = t >> 1, p = t & 1;
        const int rowA = (p == 0) ? u : 10 + u;        // i or g
        const int rowB = (p == 0) ? 5 + u : 15 + u;    // f or o
        const float sA = (p == 0) ? 0.5f : 1.0f;       // i scaled, g not
        const float sB = 0.5f;                          // f, o scaled

        u64* L0 = &sL0[u * 18 + p * 8];
        L0[0] = pack2(sA * (bih0[rowA] + bhh0[rowA]), sB * (bih0[rowB] + bhh0[rowB]));
        L0[1] = pack2(sA * Wih0[rowA], sB * Wih0[rowB]);
        sL1[u][p][0] = pack2(sA * (bih1[rowA] + bhh1[rowA]), sB * (bih1[rowB] + bhh1[rowB]));
        #pragma unroll
        for (int k = 0; k < HID_N; ++k) {
            L0[2 + k]        = pack2(sA * Whh0[rowA * HID_N + k], sB * Whh0[rowB * HID_N + k]);
            sL1[u][p][1 + k] = pack2(sA * Wih1[rowA * HID_N + k], sB * Wih1[rowB * HID_N + k]);
            sL1[u][p][6 + k] = pack2(sA * Whh1[rowA * HID_N + k], sB * Whh1[rowB * HID_N + k]);
        }
        L0[7] = 0ull;
    }
    for (int i = t; i < HID_N * SEQ_N; i += TPB) {
        const int u = i / SEQ_N, s = i - u * SEQ_N;
        sWf[u * (SEQ_N + 1) + s] = g_Weff[5 * s + u];
    }
    __syncthreads();

    const int lane  = t & 31;
    const int warp  = t >> 5;
    const int group = lane / 5;                 // 0..5 real, 6 = lanes 30,31
    const int u     = lane - group * 5;         // role / owned unit
    const int baseL = group * 5;

    const int  e_base = blockIdx.x * EPB + warp * 12 + group * 2;
    const bool vA = (group < 6) && (e_base < BATCH_N);
    const bool vB = (group < 6) && (e_base + 1 < BATCH_N);
    const int  eA = vA ? e_base : 0;
    const int  eB = vB ? e_base + 1 : 0;

    const float4* __restrict__ xrA = (const float4*)(x + (size_t)eA * SEQ_N);
    const float4* __restrict__ xrB = (const float4*)(x + (size_t)eB * SEQ_N);
    const u64*   __restrict__ L0   = &sL0[u * 18];
    const float* __restrict__ Wfr  = &sWf[u * (SEQ_N + 1)];

    // ---- hoist layer-1 weights into registers (22 u64, shared by A/B) ----
    u64 w1[2][11];
    #pragma unroll
    for (int p = 0; p < 2; ++p)
        #pragma unroll
        for (int k = 0; k < 11; ++k)
            w1[p][k] = sL1[u][p][k];

    const u64 HALF2 = pack2(0.5f, 0.5f);

    // dual-element state
    u64 h0v[2][HID_N], h1v[2][HID_N];
    float c0[2], c1[2], accS[2];
    #pragma unroll
    for (int el = 0; el < 2; ++el) {
        #pragma unroll
        for (int k = 0; k < HID_N; ++k) { h0v[el][k] = 0ull; h1v[el][k] = 0ull; }
        c0[el] = 0.f; c1[el] = 0.f; accS[el] = 0.f;
    }

    // ---- prologue: pipeline registers for both elements ----
    float4 xq[2];
    xq[0] = __ldg(&xrA[0]);
    xq[1] = __ldg(&xrB[0]);
    u64 ga0a[2], ga0b[2], ga1p0[2], ga1p1[2];
    #pragma unroll
    for (int el = 0; el < 2; ++el) {
        const u64 xx = pack2(xq[el].x, xq[el].x);
        ga0a[el] = fma2(L0[1], xx, L0[0]);     // h0v==0: chains reduce to B+Wx
        ga0b[el] = fma2(L0[9], xx, L0[8]);
        ga1p0[el] = w1[0][0];
        ga1p1[el] = w1[1][0];
    }

    #pragma unroll 1
    for (int s4 = 0; s4 < SEQ_N / 4; ++s4) {
        float4 xqn[2];
        if (s4 + 1 < SEQ_N / 4) {
            xqn[0] = __ldg(&xrA[s4 + 1]);
            xqn[1] = __ldg(&xrB[s4 + 1]);
        } else {
            xqn[0] = make_float4(0.f, 0.f, 0.f, 0.f);
            xqn[1] = make_float4(0.f, 0.f, 0.f, 0.f);
        }

        #pragma unroll
        for (int su = 0; su < 4; ++su) {
            const int s = 4 * s4 + su;
            float xn[2];
            #pragma unroll
            for (int el = 0; el < 2; ++el)
                xn[el] = (su == 0) ? xq[el].y : (su == 1) ? xq[el].z
                       : (su == 2) ? xq[el].w : xqn[el].x;

            // ---- layer 0 activations (both elements; independent) ----
            float h0u[2];
            #pragma unroll
            for (int el = 0; el < 2; ++el) {
                float iv, fv, gv, ov, ig, fg;
                unpack2(ga0a[el], iv, fv);
                float ti = tanh_fast(iv), tf = tanh_fast(fv);
                unpack2(fma2(pack2(ti, tf), HALF2, HALF2), ig, fg);
                unpack2(ga0b[el], gv, ov);
                float gg = tanh_fast(gv);
                float og = fmaf(0.5f, tanh_fast(ov), 0.5f);
                float c  = fmaf(fg, c0[el], ig * gg);
                c0[el] = c;
                h0u[el] = og * tanh_fast(c);
            }
            // ---- exchange full h0 for both elements ----
            #pragma unroll
            for (int el = 0; el < 2; ++el) {
                float a0 = __shfl_sync(0xffffffffu, h0u[el], baseL);
                float a1 = __shfl_sync(0xffffffffu, h0u[el], baseL + 1);
                float a2 = __shfl_sync(0xffffffffu, h0u[el], baseL + 2);
                float a3 = __shfl_sync(0xffffffffu, h0u[el], baseL + 3);
                float a4 = __shfl_sync(0xffffffffu, h0u[el], baseL + 4);
                h0v[el][0] = pack2(a0, a0);
                h0v[el][1] = pack2(a1, a1);
                h0v[el][2] = pack2(a2, a2);
                h0v[el][3] = pack2(a3, a3);
                h0v[el][4] = pack2(a4, a4);
            }

            // ---- layer 1: serial Wih1@h0 half (both elements) ----
            u64 gc[2], gd[2];
            #pragma unroll
            for (int el = 0; el < 2; ++el) {
                u64 a = ga1p0[el], b = ga1p1[el];
                #pragma unroll
                for (int k = 0; k < HID_N; ++k) {
                    a = fma2(w1[0][1 + k], h0v[el][k], a);
                    b = fma2(w1[1][1 + k], h0v[el][k], b);
                }
                gc[el] = a; gd[el] = b;
            }

            // ---- PIPELINE: full layer-0 gates for step s+1 (both) ----
            #pragma unroll
            for (int el = 0; el < 2; ++el) {
                const u64 xx = pack2(xn[el], xn[el]);
                u64 a = fma2(L0[1], xx, L0[0]);
                u64 b = fma2(L0[9], xx, L0[8]);
                #pragma unroll
                for (int k = 0; k < HID_N; ++k) {
                    a = fma2(L0[2 + k],  h0v[el][k], a);
                    b = fma2(L0[10 + k], h0v[el][k], b);
                }
                ga0a[el] = a; ga0b[el] = b;
            }

            // ---- layer 1 activations + head (shared weight load) ----
            const float wfs = Wfr[s];
            float h1u[2];
            #pragma unroll
            for (int el = 0; el < 2; ++el) {
                float iv, fv, gv, ov, ig, fg;
                unpack2(gc[el], iv, fv);
                float ti = tanh_fast(iv), tf = tanh_fast(fv);
                unpack2(fma2(pack2(ti, tf), HALF2, HALF2), ig, fg);
                unpack2(gd[el], gv, ov);
                float gg = tanh_fast(gv);
                float og = fmaf(0.5f, tanh_fast(ov), 0.5f);
                float c  = fmaf(fg, c1[el], ig * gg);
                c1[el] = c;
                h1u[el] = og * tanh_fast(c);
                accS[el] = fmaf(h1u[el], wfs, accS[el]);
            }

            // ---- exchange full h1 for both elements ----
            #pragma unroll
            for (int el = 0; el < 2; ++el) {
                float a0 = __shfl_sync(0xffffffffu, h1u[el], baseL);
                float a1 = __shfl_sync(0xffffffffu, h1u[el], baseL + 1);
                float a2 = __shfl_sync(0xffffffffu, h1u[el], baseL + 2);
                float a3 = __shfl_sync(0xffffffffu, h1u[el], baseL + 3);
                float a4 = __shfl_sync(0xffffffffu, h1u[el], baseL + 4);
                h1v[el][0] = pack2(a0, a0);
                h1v[el][1] = pack2(a1, a1);
                h1v[el][2] = pack2(a2, a2);
                h1v[el][3] = pack2(a3, a3);
                h1v[el][4] = pack2(a4, a4);
            }

            // ---- PIPELINE: recurrent half of next step's layer-1 gates ----
            #pragma unroll
            for (int el = 0; el < 2; ++el) {
                u64 a = w1[0][0], b = w1[1][0];
                #pragma unroll
                for (int k = 0; k < HID_N; ++k) {
                    a = fma2(w1[0][6 + k], h1v[el][k], a);
                    b = fma2(w1[1][6 + k], h1v[el][k], b);
                }
                ga1p0[el] = a; ga1p1[el] = b;
            }
        }
        xq[0] = xqn[0];
        xq[1] = xqn[1];
    }

    // ---- combine role partials; role 0 writes A, role 1 writes B ----
    float tot[2];
    #pragma unroll
    for (int el = 0; el < 2; ++el) {
        float p0 = __shfl_sync(0xffffffffu, accS[el], baseL);
        float p1 = __shfl_sync(0xffffffffu, accS[el], baseL + 1);
        float p2 = __shfl_sync(0xffffffffu, accS[el], baseL + 2);
        float p3 = __shfl_sync(0xffffffffu, accS[el], baseL + 3);
        float p4 = __shfl_sync(0xffffffffu, accS[el], baseL + 4);
        tot[el] = ((p0 + p1) + (p2 + p3)) + p4;
    }
    if (u == 0 && vA) out[eA] = tot[0] + g_beff;
    if (u == 1 && vB) out[eB] = tot[1] + g_beff;
}

// ---------------------------------------------------------------------------
// Harness entry. Inputs in metadata order:
// x, Wih0, Whh0, bih0, bhh0, Wih1, Whh1, bih1, bhh1, W1, b1, W2, b2
// ---------------------------------------------------------------------------
extern "C" void kernel_launch(void* const* d_in, const int* in_sizes, int n_in,
                              void* d_out, int out_size)
{
    const float* x    = (const float*)d_in[0];
    const float* Wih0 = (const float*)d_in[1];
    const float* Whh0 = (const float*)d_in[2];
    const float* bih0 = (const float*)d_in[3];
    const float* bhh0 = (const float*)d_in[4];
    const float* Wih1 = (const float*)d_in[5];
    const float* Whh1 = (const float*)d_in[6];
    const float* bih1 = (const float*)d_in[7];
    const float* bhh1 = (const float*)d_in[8];
    const float* W1   = (const float*)d_in[9];
    const float* b1   = (const float*)d_in[10];
    const float* W2   = (const float*)d_in[11];
    const float* b2   = (const float*)d_in[12];
    float* out = (float*)d_out;

    weff_kernel<<<(FLAT_N + 511) / 512, 512>>>(W1, b1, W2, b2);

    // 2.5 threads/element: 5-lane groups each own 2 elements.
    // 320-thread blocks (10 warps = 2.5 warps/SMSP), 120 elems/block, one wave.
    const int nblocks = (BATCH_N + EPB - 1) / EPB;   // 137 <= 148 SMs
    lstm_fused_kernel<<<nblocks, TPB>>>(x, Wih0, Whh0, bih0, bhh0,
                                        Wih1, Whh1, bih1, bhh1, out);
}